// round 15
// baseline (speedup 1.0000x reference)
#include <cuda_runtime.h>
#include <cuda_fp16.h>
#include <cstdint>

// Problem constants
#define BATCH 256
#define EMB   1024
#define SEQ   100
#define NHEAD 16
#define HDIM  64
#define MROWS (BATCH * SEQ)   // 25600

// GEMM tiling: 128x128 CTA tile, 4 warps (2x2), 64x64 warp tile
#define BM 128
#define BN 128
#define BK 64
#define STAGES 3
#define GEMM_THREADS 128
#define ROW_B     144                    // 128B data + 16B pad (conflict-free ldmatrix)
#define MAT_BYTES (128 * ROW_B)          // 18432
#define STAGE_BYTES (2 * MAT_BYTES)      // 36864
#define GEMM_SMEM (STAGES * STAGE_BYTES) // 110592

// ---------------- scratch (__device__ globals; no allocation) ----------------
__device__ __half g_xf[(size_t)MROWS * EMB];          // [b*S+s][e]
__device__ __half g_wt[(size_t)4 * EMB * EMB];        // [mat][n][k] = W[k][n]
__device__ __half g_q[(size_t)MROWS * EMB];           // [b][h][s][d]
__device__ __half g_k[(size_t)MROWS * EMB];           // [b][h][s][d]
__device__ __half g_v[(size_t)MROWS * EMB];           // [b][h][s][d]
__device__ __half g_att[(size_t)MROWS * EMB];         // [b*S+s][e]

// ---------------- helpers ----------------
__device__ __forceinline__ uint32_t smem_u32(const void* p) {
    return (uint32_t)__cvta_generic_to_shared(p);
}
__device__ __forceinline__ void cp16(uint32_t dst, const void* src) {
    asm volatile("cp.async.cg.shared.global [%0], [%1], 16;" :: "r"(dst), "l"(src));
}
__device__ __forceinline__ void ldmx4(uint32_t addr, uint32_t* r) {
    asm volatile("ldmatrix.sync.aligned.m8n8.x4.shared.b16 {%0,%1,%2,%3}, [%4];"
                 : "=r"(r[0]), "=r"(r[1]), "=r"(r[2]), "=r"(r[3]) : "r"(addr));
}
__device__ __forceinline__ void mma_fp16(float* d, const uint32_t* a, const uint32_t* b) {
    asm volatile(
        "mma.sync.aligned.m16n8k16.row.col.f32.f16.f16.f32 "
        "{%0,%1,%2,%3}, {%4,%5,%6,%7}, {%8,%9}, {%0,%1,%2,%3};"
        : "+f"(d[0]), "+f"(d[1]), "+f"(d[2]), "+f"(d[3])
        : "r"(a[0]), "r"(a[1]), "r"(a[2]), "r"(a[3]), "r"(b[0]), "r"(b[1]));
}

// ---------------- kernel 1: x [B,E,S] -> xflat fp16 [B*S, E], + pos ----------
__global__ void transpose_pos_kernel(const float* __restrict__ x,
                                     const float* __restrict__ pos,
                                     __half* __restrict__ xf) {
    __shared__ float tile[32][33];
    int b  = blockIdx.z;
    int e0 = blockIdx.y * 32;
    int s0 = blockIdx.x * 32;
    int tx = threadIdx.x, ty = threadIdx.y;

    int s = s0 + tx;
    if (s < SEQ)
        tile[ty][tx] = x[(size_t)b * EMB * SEQ + (size_t)(e0 + ty) * SEQ + s];
    __syncthreads();

    int s2 = s0 + ty, e2 = e0 + tx;
    if (s2 < SEQ) {
        float v = tile[tx][ty] + pos[(size_t)s2 * EMB + e2];
        xf[((size_t)b * SEQ + s2) * EMB + e2] = __float2half(v);
    }
}

// ---------------- kernel 2: weight transpose: W[k][n] -> WT[n][k] fp16 ------
__global__ void wconvert_kernel(const float* __restrict__ W,
                                __half* __restrict__ t_out) {
    __shared__ float t[32][33];
    int n0 = blockIdx.x * 32, k0 = blockIdx.y * 32;
    int tx = threadIdx.x, ty = threadIdx.y;
    t[ty][tx] = W[(size_t)(k0 + ty) * EMB + n0 + tx];
    __syncthreads();
    t_out[(size_t)(n0 + ty) * EMB + k0 + tx] = __float2half(t[tx][ty]);
}

// ---------------- kernel 3: fp16 HMMA GEMM (BK=64, 64x64 warp tile) --------
// C = A[M,K] @ B^T[N,K] + bias
// MODE 0: fused QKV, N = 3072; per-CTA mat select; half2 store to [b,h,s,d].
// MODE 1: O projection, N = 1024; smem-staged coalesced store to out [b,n,s].
__device__ __forceinline__ void load_stage(
    char* sb, const __half* __restrict__ A, const __half* __restrict__ B,
    int bm, int bn, int k0, int tid) {
    uint32_t sbase = smem_u32(sb);
#pragma unroll
    for (int i = 0; i < 8; i++) {
        int idx = tid + i * GEMM_THREADS;     // 0..1023
        int row = idx >> 3, c16 = idx & 7;    // 8 x 16B chunks per 128B row
        uint32_t dst = sbase + (uint32_t)(row * ROW_B + c16 * 16);
        cp16(dst,             A + (size_t)(bm + row) * EMB + k0 + c16 * 8);
        cp16(dst + MAT_BYTES, B + (size_t)(bn + row) * EMB + k0 + c16 * 8);
    }
    asm volatile("cp.async.commit_group;" ::: "memory");
}

#define CS_STRIDE 132

template <int MODE>
__global__ __launch_bounds__(GEMM_THREADS, 2)
void gemm_tc(const __half* __restrict__ A, const __half* __restrict__ B,
             const float* __restrict__ bias0, const float* __restrict__ bias1,
             const float* __restrict__ bias2,
             void* __restrict__ C0v, void* __restrict__ C1v, void* __restrict__ C2v) {
    extern __shared__ char dsm[];
    const int tid = threadIdx.x;
    const int lane = tid & 31;
    const int wid = tid >> 5;
    const int warpM = wid & 1;        // 2 warps along M (64 rows each)
    const int warpN = wid >> 1;       // 2 warps along N (64 cols each)
    const int bm = blockIdx.y * BM;
    const int bn = blockIdx.x * BN;

    const int mat = bn >> 10;
    void* Cv = (MODE == 0) ? (mat == 0 ? C0v : (mat == 1 ? C1v : C2v)) : C0v;
    const float* bias = (MODE == 0) ? (mat == 0 ? bias0 : (mat == 1 ? bias1 : bias2)) : bias0;

    float acc[4][8][4];
#pragma unroll
    for (int i = 0; i < 4; i++)
#pragma unroll
        for (int j = 0; j < 8; j++)
#pragma unroll
            for (int r = 0; r < 4; r++) acc[i][j][r] = 0.f;

    load_stage(dsm + 0 * STAGE_BYTES, A, B, bm, bn, 0 * BK, tid);
    load_stage(dsm + 1 * STAGE_BYTES, A, B, bm, bn, 1 * BK, tid);

    const int NK = EMB / BK;          // 16

    const uint32_t a_row = (uint32_t)(warpM * 64 + (lane & 15));
    const uint32_t a_koff = (uint32_t)((lane >> 4) * 16);
    const uint32_t b_row = (uint32_t)(warpN * 64 + (lane & 7) + ((lane >> 4) & 1) * 8);
    const uint32_t b_koff = (uint32_t)(((lane >> 3) & 1) * 16);

    for (int kc = 0; kc < NK; kc++) {
        asm volatile("cp.async.wait_group %0;" :: "n"(STAGES - 2) : "memory");
        __syncthreads();

        if (kc + STAGES - 1 < NK) {
            load_stage(dsm + ((kc + STAGES - 1) % STAGES) * STAGE_BYTES,
                       A, B, bm, bn, (kc + STAGES - 1) * BK, tid);
        } else {
            asm volatile("cp.async.commit_group;" ::: "memory");
        }

        uint32_t sb = smem_u32(dsm) + (uint32_t)((kc % STAGES) * STAGE_BYTES);
        uint32_t sA = sb, sB = sb + MAT_BYTES;

#pragma unroll
        for (int ks = 0; ks < 4; ks++) {          // 4 K=16 slices per BK=64
            const uint32_t kb = (uint32_t)(ks * 32);  // bytes
            uint32_t af[4][4], bf[4][4];
#pragma unroll
            for (int mi = 0; mi < 4; mi++)
                ldmx4(sA + (a_row + mi * 16) * ROW_B + kb + a_koff, af[mi]);
#pragma unroll
            for (int nb = 0; nb < 4; nb++)
                ldmx4(sB + (b_row + nb * 16) * ROW_B + kb + b_koff, bf[nb]);
#pragma unroll
            for (int mi = 0; mi < 4; mi++)
#pragma unroll
                for (int ni = 0; ni < 8; ni++)
                    mma_fp16(acc[mi][ni], af[mi], &bf[ni >> 1][(ni & 1) * 2]);
        }
    }

    const int r0 = lane >> 2;
    const int c0 = (lane & 3) * 2;

    if (MODE == 0) {
        // half2 store to [b, h, s, d] — d pairs contiguous
        __half* C = (__half*)Cv;
#pragma unroll
        for (int mi = 0; mi < 4; mi++) {
            int mbase = bm + warpM * 64 + mi * 16;
#pragma unroll
            for (int ni = 0; ni < 8; ni++) {
                int n = bn + warpN * 64 + ni * 8 + c0;
                int nn = n & 1023;
                int hh = nn >> 6, d = nn & 63;
                float bia0 = bias[nn], bia1 = bias[nn + 1];
#pragma unroll
                for (int half = 0; half < 2; half++) {
                    int m = mbase + r0 + half * 8;
                    int bb = m / SEQ, s = m - bb * SEQ;
                    float v0 = acc[mi][ni][half * 2 + 0] + bia0;
                    float v1 = acc[mi][ni][half * 2 + 1] + bia1;
                    size_t base = (((size_t)bb * NHEAD + hh) * SEQ + s) * HDIM + d;
                    *reinterpret_cast<__half2*>(&C[base]) = __floats2half2_rn(v0, v1);
                }
            }
        }
    } else {
        // stage into smem [n][m], then coalesced write to out [b, n, s]
        asm volatile("cp.async.wait_group 0;" ::: "memory");
        __syncthreads();
        float* Cs = (float*)dsm;
#pragma unroll
        for (int mi = 0; mi < 4; mi++) {
            int mloc0 = warpM * 64 + mi * 16;
#pragma unroll
            for (int ni = 0; ni < 8; ni++) {
                int nloc = warpN * 64 + ni * 8 + c0;
                float bia0 = bias[bn + nloc], bia1 = bias[bn + nloc + 1];
#pragma unroll
                for (int half = 0; half < 2; half++) {
                    int mloc = mloc0 + r0 + half * 8;
                    Cs[nloc * CS_STRIDE + mloc]       = acc[mi][ni][half * 2 + 0] + bia0;
                    Cs[(nloc + 1) * CS_STRIDE + mloc] = acc[mi][ni][half * 2 + 1] + bia1;
                }
            }
        }
        __syncthreads();
        float* C = (float*)Cv;
#pragma unroll
        for (int nr = 0; nr < 32; nr++) {
            int nloc = wid * 32 + nr;
            int n = bn + nloc;
#pragma unroll
            for (int t = 0; t < 4; t++) {
                int mloc = lane + 32 * t;
                int m = bm + mloc;
                int bb = m / SEQ, s = m - bb * SEQ;
                C[((size_t)bb * EMB + n) * SEQ + s] = Cs[nloc * CS_STRIDE + mloc];
            }
        }
    }
}

// ---------------- kernel 4: HMMA attention per (b,h) ----------------
// q,k,v fp16 [b,h,s,d]; writes attn probs (optional) and att fp16 [b*S+s][e]
// M padded to 128 (8 warps x m16); score/KV cols padded to 112.
#define MPAD 128
#define SPAD 112
#define QF_STR 72        // halves (144B rows)
#define VF_STR 120       // halves (240B rows)
#define PF_STR 120
#define PS_STR 116       // floats
#define OFF_QF 0
#define OFF_KF 18432                              // Qf: 128*72*2
#define OFF_VF (OFF_KF + 16128)                   // Kf: 112*72*2 -> 34560
#define OFF_PS (OFF_VF + 15360)                   // Vf: 64*120*2 -> 49920
#define ATT_SMEM (OFF_PS + MPAD * PS_STR * 4)     // 49920 + 59392 = 109312
__global__ __launch_bounds__(256, 2)
void attention_kernel(const __half* __restrict__ Q, const __half* __restrict__ Kg,
                      const __half* __restrict__ V,
                      __half* __restrict__ att,
                      float* __restrict__ attn_out) {
    extern __shared__ char asmem[];
    __half* Qf = (__half*)(asmem + OFF_QF);      // [128][72]  rows >= SEQ zero
    __half* Kf = (__half*)(asmem + OFF_KF);      // [112][72]  rows >= SEQ zero
    __half* Vf = (__half*)(asmem + OFF_VF);      // [64][120]  (V^T: [d][s]) cols >= SEQ zero
    __half* Pf = (__half*)(asmem + OFF_QF);      // [128][120] overlays Qf+Kf (30720 <= 34560)
    float*  Ps = (float*)(asmem + OFF_PS);       // [128][116]

    int bh = blockIdx.x;
    int b = bh >> 4, h = bh & 15;
    int tid = threadIdx.x;
    int lane = tid & 31, wid = tid >> 5;

    const __half* Qg = Q + (size_t)bh * (SEQ * HDIM);   // [s][d]
    const __half* Kp = Kg + (size_t)bh * (SEQ * HDIM);
    const __half* Vg = V + (size_t)bh * (SEQ * HDIM);

    // fill Qf (128 rows, zero-padded), Kf (112 rows, zero-padded)
    for (int idx = tid; idx < MPAD * HDIM; idx += 256) {
        int s = idx >> 6, d = idx & 63;
        __half qv = __float2half(0.f);
        if (s < SEQ) qv = Qg[s * HDIM + d];
        Qf[s * QF_STR + d] = qv;
        if (s < SPAD) {
            __half kv = __float2half(0.f);
            if (s < SEQ) kv = Kp[s * HDIM + d];
            Kf[s * QF_STR + d] = kv;
        }
    }
    // Vf transposed [d][s], cols >= SEQ zeroed
    for (int idx = tid; idx < HDIM * SPAD; idx += 256) {
        int d = idx / SPAD, s = idx - d * SPAD;
        Vf[d * VF_STR + s] = (s < SEQ) ? Vg[s * HDIM + d] : __float2half(0.f);
    }
    __syncthreads();

    const uint32_t a_row = (uint32_t)(lane & 15);
    const uint32_t a_koff = (uint32_t)((lane >> 4) * 16);
    const uint32_t b_row = (uint32_t)((lane & 7) + ((lane >> 4) & 1) * 8);
    const uint32_t b_koff = (uint32_t)(((lane >> 3) & 1) * 16);
    const int r0 = lane >> 2, c0 = (lane & 3) * 2;

    // ---- scores = Q K^T / 8 : warp w -> m16 rows [w*16, w*16+16) of 128 ----
    {
        float acc[14][4];
#pragma unroll
        for (int i = 0; i < 14; i++)
#pragma unroll
            for (int r = 0; r < 4; r++) acc[i][r] = 0.f;

        uint32_t qb = smem_u32(Qf) + (wid * 16 + a_row) * (QF_STR * 2) + a_koff;
        uint32_t kb = smem_u32(Kf) + b_row * (QF_STR * 2) + b_koff;
#pragma unroll
        for (int ks = 0; ks < 4; ks++) {
            uint32_t ko = (uint32_t)(ks * 32);
            uint32_t af[4];
            ldmx4(qb + ko, af);
#pragma unroll
            for (int nt = 0; nt < 7; nt++) {      // B rows nt*16 + b_row <= 111
                uint32_t bf[4];
                ldmx4(kb + nt * 16 * (QF_STR * 2) + ko, bf);
                mma_fp16(acc[nt * 2 + 0], af, &bf[0]);
                mma_fp16(acc[nt * 2 + 1], af, &bf[2]);
            }
        }
#pragma unroll
        for (int ni = 0; ni < 14; ni++) {
            int n = ni * 8 + c0;
            float s0 = (n < SEQ) ? acc[ni][0] * 0.125f : -1e30f;
            float s1 = (n + 1 < SEQ) ? acc[ni][1] * 0.125f : -1e30f;
            float s2 = (n < SEQ) ? acc[ni][2] * 0.125f : -1e30f;
            float s3 = (n + 1 < SEQ) ? acc[ni][3] * 0.125f : -1e30f;
            int i = wid * 16 + r0;                // i in [0,128), Ps has 128 rows
            Ps[i * PS_STR + n] = s0;
            Ps[i * PS_STR + n + 1] = s1;
            Ps[(i + 8) * PS_STR + n] = s2;
            Ps[(i + 8) * PS_STR + n + 1] = s3;
        }
    }
    __syncthreads();

    // ---- row softmax (one warp per row, rows < SEQ) ----
    for (int i = wid; i < SEQ; i += 8) {
        float* row = Ps + i * PS_STR;
        float mx = -1e30f;
        for (int j = lane; j < SPAD; j += 32) mx = fmaxf(mx, row[j]);
#pragma unroll
        for (int o = 16; o > 0; o >>= 1) mx = fmaxf(mx, __shfl_xor_sync(0xffffffffu, mx, o));
        float sum = 0.f;
        for (int j = lane; j < SPAD; j += 32) {
            float e = __expf(row[j] - mx);
            row[j] = e;
            sum += e;
        }
#pragma unroll
        for (int o = 16; o > 0; o >>= 1) sum += __shfl_xor_sync(0xffffffffu, sum, o);
        float inv = 1.0f / sum;
        for (int j = lane; j < SPAD; j += 32) row[j] *= inv;
    }
    __syncthreads();

    // ---- attn probs out + P -> fp16 (overlays Qf/Kf) ----
    if (attn_out != nullptr) {
        float* dst = attn_out + (size_t)bh * (SEQ * SEQ);
        for (int p = tid; p < SEQ * SEQ; p += 256) {
            int i = p / SEQ, j = p - (p / SEQ) * SEQ;
            dst[p] = Ps[i * PS_STR + j];
        }
    }
    for (int p = tid; p < MPAD * SPAD; p += 256) {
        int i = p / SPAD, j = p - (p / SPAD) * SPAD;
        float v = (i < SEQ) ? Ps[i * PS_STR + j] : 0.f;
        Pf[i * PF_STR + j] = __float2half(v);
    }
    __syncthreads();

    // ---- attended = P @ V : A = Pf [128 x K=112], B = Vf [d][j] ----
    {
        float acc[8][4];
#pragma unroll
        for (int i = 0; i < 8; i++)
#pragma unroll
            for (int r = 0; r < 4; r++) acc[i][r] = 0.f;

        uint32_t pb = smem_u32(Pf) + (wid * 16 + a_row) * (PF_STR * 2) + a_koff;
        uint32_t vb = smem_u32(Vf) + b_row * (VF_STR * 2) + b_koff;
#pragma unroll
        for (int ks = 0; ks < 7; ks++) {          // K = 112
            uint32_t ko = (uint32_t)(ks * 32);
            uint32_t af[4];
            ldmx4(pb + ko, af);
#pragma unroll
            for (int nt = 0; nt < 4; nt++) {      // d rows nt*16 + b_row <= 63
                uint32_t bf[4];
                ldmx4(vb + nt * 16 * (VF_STR * 2) + ko, bf);
                mma_fp16(acc[nt * 2 + 0], af, &bf[0]);
                mma_fp16(acc[nt * 2 + 1], af, &bf[2]);
            }
        }
#pragma unroll
        for (int ni = 0; ni < 8; ni++) {
            int d = ni * 8 + c0;
#pragma unroll
            for (int half = 0; half < 2; half++) {
                int i = wid * 16 + r0 + half * 8;
                if (i < SEQ) {
                    size_t dst = ((size_t)b * SEQ + i) * EMB + h * HDIM + d;
                    *reinterpret_cast<__half2*>(&att[dst]) =
                        __floats2half2_rn(acc[ni][half * 2 + 0], acc[ni][half * 2 + 1]);
                }
            }
        }
    }
}

// ---------------- launch ----------------
extern "C" void kernel_launch(void* const* d_in, const int* in_sizes, int n_in,
                              void* d_out, int out_size) {
    const float* x   = (const float*)d_in[0];
    const float* Wq  = (const float*)d_in[1];
    const float* bq  = (const float*)d_in[2];
    const float* Wk  = (const float*)d_in[3];
    const float* bk  = (const float*)d_in[4];
    const float* Wv  = (const float*)d_in[5];
    const float* bv  = (const float*)d_in[6];
    const float* Wo  = (const float*)d_in[7];
    const float* bo  = (const float*)d_in[8];
    const float* pos = (const float*)d_in[9];

    float* out = (float*)d_out;
    const size_t out_elems = (size_t)BATCH * EMB * SEQ;
    float* attn_out = ((size_t)out_size > out_elems) ? out + out_elems : nullptr;

    __half *xf, *wt, *att, *q, *k, *v;
    cudaGetSymbolAddress((void**)&xf,  g_xf);
    cudaGetSymbolAddress((void**)&wt,  g_wt);
    cudaGetSymbolAddress((void**)&q,   g_q);
    cudaGetSymbolAddress((void**)&k,   g_k);
    cudaGetSymbolAddress((void**)&v,   g_v);
    cudaGetSymbolAddress((void**)&att, g_att);

    cudaFuncSetAttribute(gemm_tc<0>, cudaFuncAttributeMaxDynamicSharedMemorySize, GEMM_SMEM);
    cudaFuncSetAttribute(gemm_tc<1>, cudaFuncAttributeMaxDynamicSharedMemorySize, GEMM_SMEM);
    cudaFuncSetAttribute(attention_kernel, cudaFuncAttributeMaxDynamicSharedMemorySize, ATT_SMEM);

    const size_t WSTRIDE = (size_t)EMB * EMB;

    // 1) weight transpose to K-major fp16
    {
        dim3 grid(EMB / 32, EMB / 32);
        dim3 blk(32, 32);
        wconvert_kernel<<<grid, blk>>>(Wq, wt + 0 * WSTRIDE);
        wconvert_kernel<<<grid, blk>>>(Wk, wt + 1 * WSTRIDE);
        wconvert_kernel<<<grid, blk>>>(Wv, wt + 2 * WSTRIDE);
        wconvert_kernel<<<grid, blk>>>(Wo, wt + 3 * WSTRIDE);
    }

    // 2) transpose + pos -> fp16
    {
        dim3 grid((SEQ + 31) / 32, EMB / 32, BATCH);
        dim3 blk(32, 32);
        transpose_pos_kernel<<<grid, blk>>>(x, pos, xf);
    }

    // 3) fused Q/K/V projection (one GEMM over N=3072)
    {
        dim3 grid(3 * EMB / BN, MROWS / BM);   // (24, 200)
        gemm_tc<0><<<grid, GEMM_THREADS, GEMM_SMEM>>>(
            xf, wt, bq, bk, bv, q, k, v);
    }

    // 4) attention (tensor cores)
    attention_kernel<<<BATCH * NHEAD, 256, ATT_SMEM>>>(q, k, v, att, attn_out);

    // 5) output projection (+ transpose back to [B, E, H, W])
    {
        dim3 grid(EMB / BN, MROWS / BM);
        gemm_tc<1><<<grid, GEMM_THREADS, GEMM_SMEM>>>(
            att, wt + 3 * WSTRIDE, bo, nullptr, nullptr, out, nullptr, nullptr);
    }
}

// round 16
// speedup vs baseline: 1.0749x; 1.0749x over previous
#include <cuda_runtime.h>
#include <cuda_fp16.h>
#include <cstdint>

// Problem constants
#define BATCH 256
#define EMB   1024
#define SEQ   100
#define NHEAD 16
#define HDIM  64
#define MROWS (BATCH * SEQ)   // 25600

// GEMM tiling: 128x128 CTA tile, 4 warps (2x2), 64x64 warp tile
#define BM 128
#define BN 128
#define BK 64
#define STAGES 3
#define GEMM_THREADS 128
#define ROW_B     144                    // 128B data + 16B pad (conflict-free ldmatrix)
#define MAT_BYTES (128 * ROW_B)          // 18432
#define STAGE_BYTES (2 * MAT_BYTES)      // 36864
#define GEMM_SMEM (STAGES * STAGE_BYTES) // 110592

// ---------------- scratch (__device__ globals; no allocation) ----------------
__device__ __half g_xf[(size_t)MROWS * EMB];          // [b*S+s][e]
__device__ __half g_wt[(size_t)4 * EMB * EMB];        // [mat][n][k] = W[k][n]
__device__ __half g_q[(size_t)MROWS * EMB];           // [b][h][s][d]
__device__ __half g_k[(size_t)MROWS * EMB];           // [b][h][s][d]
__device__ __half g_v[(size_t)MROWS * EMB];           // [b][h][s][d]
__device__ __half g_att[(size_t)MROWS * EMB];         // [b*S+s][e]

// ---------------- helpers ----------------
__device__ __forceinline__ uint32_t smem_u32(const void* p) {
    return (uint32_t)__cvta_generic_to_shared(p);
}
__device__ __forceinline__ void cp16(uint32_t dst, const void* src) {
    asm volatile("cp.async.cg.shared.global [%0], [%1], 16;" :: "r"(dst), "l"(src));
}
__device__ __forceinline__ void ldmx4(uint32_t addr, uint32_t* r) {
    asm volatile("ldmatrix.sync.aligned.m8n8.x4.shared.b16 {%0,%1,%2,%3}, [%4];"
                 : "=r"(r[0]), "=r"(r[1]), "=r"(r[2]), "=r"(r[3]) : "r"(addr));
}
__device__ __forceinline__ void mma_fp16(float* d, const uint32_t* a, const uint32_t* b) {
    asm volatile(
        "mma.sync.aligned.m16n8k16.row.col.f32.f16.f16.f32 "
        "{%0,%1,%2,%3}, {%4,%5,%6,%7}, {%8,%9}, {%0,%1,%2,%3};"
        : "+f"(d[0]), "+f"(d[1]), "+f"(d[2]), "+f"(d[3])
        : "r"(a[0]), "r"(a[1]), "r"(a[2]), "r"(a[3]), "r"(b[0]), "r"(b[1]));
}

// ---------------- kernel 1: x [B,E,S] -> xflat fp16 [B*S, E], + pos ----------
// v2: one CTA per (b, 128-e group). float4 reads, half2 coalesced writes.
#define TP_EG 128
#define TP_STR 101
#define TP_SMEM (TP_EG * TP_STR * 4)     // 51712 bytes
__global__ __launch_bounds__(256)
void transpose_pos_kernel(const float* __restrict__ x,
                          const float* __restrict__ pos,
                          __half* __restrict__ xf) {
    extern __shared__ float smt[];       // [128][101]
    const int eg = blockIdx.x;           // 0..7
    const int b  = blockIdx.y;
    const int e0 = eg * TP_EG;
    const int tid = threadIdx.x;

    // read: 128 rows x 25 float4 (x rows are 400B, 16B-aligned)
    const float4* x4 = reinterpret_cast<const float4*>(x) + ((size_t)b * EMB + e0) * 25;
#pragma unroll
    for (int i = 0; i < 13; i++) {
        int idx = tid + 256 * i;         // 0..3199
        if (idx < 3200) {
            int row = idx / 25, c4 = idx - row * 25;
            float4 v = x4[(size_t)row * 25 + c4];
            float* dst = &smt[row * TP_STR + c4 * 4];
            dst[0] = v.x; dst[1] = v.y; dst[2] = v.z; dst[3] = v.w;
        }
    }
    __syncthreads();

    // write: 100 s x 64 half2 (128B contiguous per s), add pos in fp32
#pragma unroll
    for (int i = 0; i < 25; i++) {
        int idx = tid + 256 * i;         // 0..6399
        int s = idx >> 6, ep = idx & 63;
        int el = ep * 2;
        float f0 = smt[(el + 0) * TP_STR + s] + pos[(size_t)s * EMB + e0 + el + 0];
        float f1 = smt[(el + 1) * TP_STR + s] + pos[(size_t)s * EMB + e0 + el + 1];
        size_t o = ((size_t)b * SEQ + s) * EMB + e0 + el;
        *reinterpret_cast<__half2*>(&xf[o]) = __floats2half2_rn(f0, f1);
    }
}

// ---------------- kernel 2: weight transpose (all 4 mats in one launch) -----
__global__ void wconvert_kernel(const float* __restrict__ W0,
                                const float* __restrict__ W1,
                                const float* __restrict__ W2,
                                const float* __restrict__ W3,
                                __half* __restrict__ wt_base) {
    __shared__ float t[32][33];
    const int mat = blockIdx.z;
    const float* W = (mat == 0) ? W0 : (mat == 1) ? W1 : (mat == 2) ? W2 : W3;
    __half* t_out = wt_base + (size_t)mat * EMB * EMB;
    int n0 = blockIdx.x * 32, k0 = blockIdx.y * 32;
    int tx = threadIdx.x, ty = threadIdx.y;
    t[ty][tx] = W[(size_t)(k0 + ty) * EMB + n0 + tx];
    __syncthreads();
    t_out[(size_t)(n0 + ty) * EMB + k0 + tx] = __float2half(t[tx][ty]);
}

// ---------------- kernel 3: fp16 HMMA GEMM (BK=64, 64x64 warp tile) --------
// C = A[M,K] @ B^T[N,K] + bias
// MODE 0: fused QKV, N = 3072; per-CTA mat select; half2 store to [b,h,s,d].
// MODE 1: O projection, N = 1024; smem-staged coalesced store to out [b,n,s].
__device__ __forceinline__ void load_stage(
    char* sb, const __half* __restrict__ A, const __half* __restrict__ B,
    int bm, int bn, int k0, int tid) {
    uint32_t sbase = smem_u32(sb);
#pragma unroll
    for (int i = 0; i < 8; i++) {
        int idx = tid + i * GEMM_THREADS;     // 0..1023
        int row = idx >> 3, c16 = idx & 7;    // 8 x 16B chunks per 128B row
        uint32_t dst = sbase + (uint32_t)(row * ROW_B + c16 * 16);
        cp16(dst,             A + (size_t)(bm + row) * EMB + k0 + c16 * 8);
        cp16(dst + MAT_BYTES, B + (size_t)(bn + row) * EMB + k0 + c16 * 8);
    }
    asm volatile("cp.async.commit_group;" ::: "memory");
}

#define CS_STRIDE 132

template <int MODE>
__global__ __launch_bounds__(GEMM_THREADS, 2)
void gemm_tc(const __half* __restrict__ A, const __half* __restrict__ B,
             const float* __restrict__ bias0, const float* __restrict__ bias1,
             const float* __restrict__ bias2,
             void* __restrict__ C0v, void* __restrict__ C1v, void* __restrict__ C2v) {
    extern __shared__ char dsm[];
    const int tid = threadIdx.x;
    const int lane = tid & 31;
    const int wid = tid >> 5;
    const int warpM = wid & 1;        // 2 warps along M (64 rows each)
    const int warpN = wid >> 1;       // 2 warps along N (64 cols each)
    const int bm = blockIdx.y * BM;
    const int bn = blockIdx.x * BN;

    const int mat = bn >> 10;
    void* Cv = (MODE == 0) ? (mat == 0 ? C0v : (mat == 1 ? C1v : C2v)) : C0v;
    const float* bias = (MODE == 0) ? (mat == 0 ? bias0 : (mat == 1 ? bias1 : bias2)) : bias0;

    float acc[4][8][4];
#pragma unroll
    for (int i = 0; i < 4; i++)
#pragma unroll
        for (int j = 0; j < 8; j++)
#pragma unroll
            for (int r = 0; r < 4; r++) acc[i][j][r] = 0.f;

    load_stage(dsm + 0 * STAGE_BYTES, A, B, bm, bn, 0 * BK, tid);
    load_stage(dsm + 1 * STAGE_BYTES, A, B, bm, bn, 1 * BK, tid);

    const int NK = EMB / BK;          // 16

    const uint32_t a_row = (uint32_t)(warpM * 64 + (lane & 15));
    const uint32_t a_koff = (uint32_t)((lane >> 4) * 16);
    const uint32_t b_row = (uint32_t)(warpN * 64 + (lane & 7) + ((lane >> 4) & 1) * 8);
    const uint32_t b_koff = (uint32_t)(((lane >> 3) & 1) * 16);

    for (int kc = 0; kc < NK; kc++) {
        asm volatile("cp.async.wait_group %0;" :: "n"(STAGES - 2) : "memory");
        __syncthreads();

        if (kc + STAGES - 1 < NK) {
            load_stage(dsm + ((kc + STAGES - 1) % STAGES) * STAGE_BYTES,
                       A, B, bm, bn, (kc + STAGES - 1) * BK, tid);
        } else {
            asm volatile("cp.async.commit_group;" ::: "memory");
        }

        uint32_t sb = smem_u32(dsm) + (uint32_t)((kc % STAGES) * STAGE_BYTES);
        uint32_t sA = sb, sB = sb + MAT_BYTES;

#pragma unroll
        for (int ks = 0; ks < 4; ks++) {          // 4 K=16 slices per BK=64
            const uint32_t kb = (uint32_t)(ks * 32);  // bytes
            uint32_t af[4][4], bf[4][4];
#pragma unroll
            for (int mi = 0; mi < 4; mi++)
                ldmx4(sA + (a_row + mi * 16) * ROW_B + kb + a_koff, af[mi]);
#pragma unroll
            for (int nb = 0; nb < 4; nb++)
                ldmx4(sB + (b_row + nb * 16) * ROW_B + kb + b_koff, bf[nb]);
#pragma unroll
            for (int mi = 0; mi < 4; mi++)
#pragma unroll
                for (int ni = 0; ni < 8; ni++)
                    mma_fp16(acc[mi][ni], af[mi], &bf[ni >> 1][(ni & 1) * 2]);
        }
    }

    const int r0 = lane >> 2;
    const int c0 = (lane & 3) * 2;

    if (MODE == 0) {
        // half2 store to [b, h, s, d] — d pairs contiguous
        __half* C = (__half*)Cv;
#pragma unroll
        for (int mi = 0; mi < 4; mi++) {
            int mbase = bm + warpM * 64 + mi * 16;
#pragma unroll
            for (int ni = 0; ni < 8; ni++) {
                int n = bn + warpN * 64 + ni * 8 + c0;
                int nn = n & 1023;
                int hh = nn >> 6, d = nn & 63;
                float bia0 = bias[nn], bia1 = bias[nn + 1];
#pragma unroll
                for (int half = 0; half < 2; half++) {
                    int m = mbase + r0 + half * 8;
                    int bb = m / SEQ, s = m - bb * SEQ;
                    float v0 = acc[mi][ni][half * 2 + 0] + bia0;
                    float v1 = acc[mi][ni][half * 2 + 1] + bia1;
                    size_t base = (((size_t)bb * NHEAD + hh) * SEQ + s) * HDIM + d;
                    *reinterpret_cast<__half2*>(&C[base]) = __floats2half2_rn(v0, v1);
                }
            }
        }
    } else {
        // stage into smem [n][m], then coalesced write to out [b, n, s]
        asm volatile("cp.async.wait_group 0;" ::: "memory");
        __syncthreads();
        float* Cs = (float*)dsm;
#pragma unroll
        for (int mi = 0; mi < 4; mi++) {
            int mloc0 = warpM * 64 + mi * 16;
#pragma unroll
            for (int ni = 0; ni < 8; ni++) {
                int nloc = warpN * 64 + ni * 8 + c0;
                float bia0 = bias[bn + nloc], bia1 = bias[bn + nloc + 1];
#pragma unroll
                for (int half = 0; half < 2; half++) {
                    int mloc = mloc0 + r0 + half * 8;
                    Cs[nloc * CS_STRIDE + mloc]       = acc[mi][ni][half * 2 + 0] + bia0;
                    Cs[(nloc + 1) * CS_STRIDE + mloc] = acc[mi][ni][half * 2 + 1] + bia1;
                }
            }
        }
        __syncthreads();
        float* C = (float*)Cv;
#pragma unroll
        for (int nr = 0; nr < 32; nr++) {
            int nloc = wid * 32 + nr;
            int n = bn + nloc;
#pragma unroll
            for (int t = 0; t < 4; t++) {
                int mloc = lane + 32 * t;
                int m = bm + mloc;
                int bb = m / SEQ, s = m - bb * SEQ;
                C[((size_t)bb * EMB + n) * SEQ + s] = Cs[nloc * CS_STRIDE + mloc];
            }
        }
    }
}

// ---------------- kernel 4: HMMA attention per (b,h) ----------------
// q,k,v fp16 [b,h,s,d]; writes attn probs (optional) and att fp16 [b*S+s][e]
// M padded to 128 (8 warps x m16); score/KV cols padded to 112.
#define MPAD 128
#define SPAD 112
#define QF_STR 72        // halves (144B rows)
#define VF_STR 120       // halves (240B rows)
#define PF_STR 120
#define PS_STR 116       // floats
#define OFF_QF 0
#define OFF_KF 18432                              // Qf: 128*72*2
#define OFF_VF (OFF_KF + 16128)                   // Kf: 112*72*2 -> 34560
#define OFF_PS (OFF_VF + 15360)                   // Vf: 64*120*2 -> 49920
#define ATT_SMEM (OFF_PS + MPAD * PS_STR * 4)     // 49920 + 59392 = 109312
__global__ __launch_bounds__(256, 2)
void attention_kernel(const __half* __restrict__ Q, const __half* __restrict__ Kg,
                      const __half* __restrict__ V,
                      __half* __restrict__ att,
                      float* __restrict__ attn_out) {
    extern __shared__ char asmem[];
    __half* Qf = (__half*)(asmem + OFF_QF);      // [128][72]  rows >= SEQ zero
    __half* Kf = (__half*)(asmem + OFF_KF);      // [112][72]  rows >= SEQ zero
    __half* Vf = (__half*)(asmem + OFF_VF);      // [64][120]  (V^T: [d][s]) cols >= SEQ zero
    __half* Pf = (__half*)(asmem + OFF_QF);      // [128][120] overlays Qf+Kf (30720 <= 34560)
    float*  Ps = (float*)(asmem + OFF_PS);       // [128][116]

    int bh = blockIdx.x;
    int b = bh >> 4, h = bh & 15;
    int tid = threadIdx.x;
    int lane = tid & 31, wid = tid >> 5;

    const __half* Qg = Q + (size_t)bh * (SEQ * HDIM);   // [s][d]
    const __half* Kp = Kg + (size_t)bh * (SEQ * HDIM);
    const __half* Vg = V + (size_t)bh * (SEQ * HDIM);

    // fill Qf (128 rows, zero-padded), Kf (112 rows, zero-padded)
    for (int idx = tid; idx < MPAD * HDIM; idx += 256) {
        int s = idx >> 6, d = idx & 63;
        __half qv = __float2half(0.f);
        if (s < SEQ) qv = Qg[s * HDIM + d];
        Qf[s * QF_STR + d] = qv;
        if (s < SPAD) {
            __half kv = __float2half(0.f);
            if (s < SEQ) kv = Kp[s * HDIM + d];
            Kf[s * QF_STR + d] = kv;
        }
    }
    // Vf transposed [d][s], cols >= SEQ zeroed
    for (int idx = tid; idx < HDIM * SPAD; idx += 256) {
        int d = idx / SPAD, s = idx - d * SPAD;
        Vf[d * VF_STR + s] = (s < SEQ) ? Vg[s * HDIM + d] : __float2half(0.f);
    }
    __syncthreads();

    const uint32_t a_row = (uint32_t)(lane & 15);
    const uint32_t a_koff = (uint32_t)((lane >> 4) * 16);
    const uint32_t b_row = (uint32_t)((lane & 7) + ((lane >> 4) & 1) * 8);
    const uint32_t b_koff = (uint32_t)(((lane >> 3) & 1) * 16);
    const int r0 = lane >> 2, c0 = (lane & 3) * 2;

    // ---- scores = Q K^T / 8 : warp w -> m16 rows [w*16, w*16+16) of 128 ----
    {
        float acc[14][4];
#pragma unroll
        for (int i = 0; i < 14; i++)
#pragma unroll
            for (int r = 0; r < 4; r++) acc[i][r] = 0.f;

        uint32_t qb = smem_u32(Qf) + (wid * 16 + a_row) * (QF_STR * 2) + a_koff;
        uint32_t kb = smem_u32(Kf) + b_row * (QF_STR * 2) + b_koff;
#pragma unroll
        for (int ks = 0; ks < 4; ks++) {
            uint32_t ko = (uint32_t)(ks * 32);
            uint32_t af[4];
            ldmx4(qb + ko, af);
#pragma unroll
            for (int nt = 0; nt < 7; nt++) {      // B rows nt*16 + b_row <= 111
                uint32_t bf[4];
                ldmx4(kb + nt * 16 * (QF_STR * 2) + ko, bf);
                mma_fp16(acc[nt * 2 + 0], af, &bf[0]);
                mma_fp16(acc[nt * 2 + 1], af, &bf[2]);
            }
        }
#pragma unroll
        for (int ni = 0; ni < 14; ni++) {
            int n = ni * 8 + c0;
            float s0 = (n < SEQ) ? acc[ni][0] * 0.125f : -1e30f;
            float s1 = (n + 1 < SEQ) ? acc[ni][1] * 0.125f : -1e30f;
            float s2 = (n < SEQ) ? acc[ni][2] * 0.125f : -1e30f;
            float s3 = (n + 1 < SEQ) ? acc[ni][3] * 0.125f : -1e30f;
            int i = wid * 16 + r0;                // i in [0,128), Ps has 128 rows
            Ps[i * PS_STR + n] = s0;
            Ps[i * PS_STR + n + 1] = s1;
            Ps[(i + 8) * PS_STR + n] = s2;
            Ps[(i + 8) * PS_STR + n + 1] = s3;
        }
    }
    __syncthreads();

    // ---- row softmax (one warp per row, rows < SEQ) ----
    for (int i = wid; i < SEQ; i += 8) {
        float* row = Ps + i * PS_STR;
        float mx = -1e30f;
        for (int j = lane; j < SPAD; j += 32) mx = fmaxf(mx, row[j]);
#pragma unroll
        for (int o = 16; o > 0; o >>= 1) mx = fmaxf(mx, __shfl_xor_sync(0xffffffffu, mx, o));
        float sum = 0.f;
        for (int j = lane; j < SPAD; j += 32) {
            float e = __expf(row[j] - mx);
            row[j] = e;
            sum += e;
        }
#pragma unroll
        for (int o = 16; o > 0; o >>= 1) sum += __shfl_xor_sync(0xffffffffu, sum, o);
        float inv = 1.0f / sum;
        for (int j = lane; j < SPAD; j += 32) row[j] *= inv;
    }
    __syncthreads();

    // ---- attn probs out + P -> fp16 (overlays Qf/Kf) ----
    if (attn_out != nullptr) {
        float* dst = attn_out + (size_t)bh * (SEQ * SEQ);
        for (int p = tid; p < SEQ * SEQ; p += 256) {
            int i = p / SEQ, j = p - (p / SEQ) * SEQ;
            dst[p] = Ps[i * PS_STR + j];
        }
    }
    for (int p = tid; p < MPAD * SPAD; p += 256) {
        int i = p / SPAD, j = p - (p / SPAD) * SPAD;
        float v = (i < SEQ) ? Ps[i * PS_STR + j] : 0.f;
        Pf[i * PF_STR + j] = __float2half(v);
    }
    __syncthreads();

    // ---- attended = P @ V : A = Pf [128 x K=112], B = Vf [d][j] ----
    {
        float acc[8][4];
#pragma unroll
        for (int i = 0; i < 8; i++)
#pragma unroll
            for (int r = 0; r < 4; r++) acc[i][r] = 0.f;

        uint32_t pb = smem_u32(Pf) + (wid * 16 + a_row) * (PF_STR * 2) + a_koff;
        uint32_t vb = smem_u32(Vf) + b_row * (VF_STR * 2) + b_koff;
#pragma unroll
        for (int ks = 0; ks < 7; ks++) {          // K = 112
            uint32_t ko = (uint32_t)(ks * 32);
            uint32_t af[4];
            ldmx4(pb + ko, af);
#pragma unroll
            for (int nt = 0; nt < 4; nt++) {      // d rows nt*16 + b_row <= 63
                uint32_t bf[4];
                ldmx4(vb + nt * 16 * (VF_STR * 2) + ko, bf);
                mma_fp16(acc[nt * 2 + 0], af, &bf[0]);
                mma_fp16(acc[nt * 2 + 1], af, &bf[2]);
            }
        }
#pragma unroll
        for (int ni = 0; ni < 8; ni++) {
            int d = ni * 8 + c0;
#pragma unroll
            for (int half = 0; half < 2; half++) {
                int i = wid * 16 + r0 + half * 8;
                if (i < SEQ) {
                    size_t dst = ((size_t)b * SEQ + i) * EMB + h * HDIM + d;
                    *reinterpret_cast<__half2*>(&att[dst]) =
                        __floats2half2_rn(acc[ni][half * 2 + 0], acc[ni][half * 2 + 1]);
                }
            }
        }
    }
}

// ---------------- launch ----------------
extern "C" void kernel_launch(void* const* d_in, const int* in_sizes, int n_in,
                              void* d_out, int out_size) {
    const float* x   = (const float*)d_in[0];
    const float* Wq  = (const float*)d_in[1];
    const float* bq  = (const float*)d_in[2];
    const float* Wk  = (const float*)d_in[3];
    const float* bk  = (const float*)d_in[4];
    const float* Wv  = (const float*)d_in[5];
    const float* bv  = (const float*)d_in[6];
    const float* Wo  = (const float*)d_in[7];
    const float* bo  = (const float*)d_in[8];
    const float* pos = (const float*)d_in[9];

    float* out = (float*)d_out;
    const size_t out_elems = (size_t)BATCH * EMB * SEQ;
    float* attn_out = ((size_t)out_size > out_elems) ? out + out_elems : nullptr;

    __half *xf, *wt, *att, *q, *k, *v;
    cudaGetSymbolAddress((void**)&xf,  g_xf);
    cudaGetSymbolAddress((void**)&wt,  g_wt);
    cudaGetSymbolAddress((void**)&q,   g_q);
    cudaGetSymbolAddress((void**)&k,   g_k);
    cudaGetSymbolAddress((void**)&v,   g_v);
    cudaGetSymbolAddress((void**)&att, g_att);

    cudaFuncSetAttribute(gemm_tc<0>, cudaFuncAttributeMaxDynamicSharedMemorySize, GEMM_SMEM);
    cudaFuncSetAttribute(gemm_tc<1>, cudaFuncAttributeMaxDynamicSharedMemorySize, GEMM_SMEM);
    cudaFuncSetAttribute(attention_kernel, cudaFuncAttributeMaxDynamicSharedMemorySize, ATT_SMEM);
    cudaFuncSetAttribute(transpose_pos_kernel, cudaFuncAttributeMaxDynamicSharedMemorySize, TP_SMEM);

    // 1) weight transpose to K-major fp16 (all 4 matrices, one launch)
    {
        dim3 grid(EMB / 32, EMB / 32, 4);
        dim3 blk(32, 32);
        wconvert_kernel<<<grid, blk>>>(Wq, Wk, Wv, Wo, wt);
    }

    // 2) transpose + pos -> fp16 (vectorized, 1 CTA per (b, 128-e group))
    {
        dim3 grid(EMB / TP_EG, BATCH);   // (8, 256)
        transpose_pos_kernel<<<grid, 256, TP_SMEM>>>(x, pos, xf);
    }

    // 3) fused Q/K/V projection (one GEMM over N=3072)
    {
        dim3 grid(3 * EMB / BN, MROWS / BM);   // (24, 200)
        gemm_tc<0><<<grid, GEMM_THREADS, GEMM_SMEM>>>(
            xf, wt, bq, bk, bv, q, k, v);
    }

    // 4) attention (tensor cores)
    attention_kernel<<<BATCH * NHEAD, 256, ATT_SMEM>>>(q, k, v, att, attn_out);

    // 5) output projection (+ transpose back to [B, E, H, W])
    {
        dim3 grid(EMB / BN, MROWS / BM);
        gemm_tc<1><<<grid, GEMM_THREADS, GEMM_SMEM>>>(
            att, wt + 3 * EMB * EMB, bo, nullptr, nullptr, out, nullptr, nullptr);
    }
}